// round 1
// baseline (speedup 1.0000x reference)
#include <cuda_runtime.h>
#include <math.h>

#define Bb 2
#define Ss 2048
#define Dd 1024
#define Hh 16
#define DKk 64
#define TQ 4
#define TH 0.1f

// Scratch (allocation-free rule: __device__ globals)
__device__ float g_q[Bb*Ss*Dd];
__device__ float g_k[Bb*Ss*Dd];
__device__ float g_v[Bb*Ss*Dd];
__device__ float g_m[Bb*Ss*Dd];

// ---------------------------------------------------------------------------
// C[M,N] = A[M,K] @ W[N,K]^T + bias   (torch Linear)
// 64x64 block tile, BK=16, 256 threads, 4x4 per thread, float4 loads.
// M,N,K all multiples of 64/16 here.
// ---------------------------------------------------------------------------
__global__ __launch_bounds__(256) void gemm_bias(
    const float* __restrict__ A, const float* __restrict__ W,
    const float* __restrict__ bias, float* __restrict__ C,
    int M, int N, int K)
{
    __shared__ float As[16][68];
    __shared__ float Ws[16][68];
    const int tid = threadIdx.x;
    const int tx = tid & 15, ty = tid >> 4;
    const int m0 = blockIdx.y * 64, n0 = blockIdx.x * 64;
    const int lm = tid >> 2;           // 0..63
    const int lk = (tid & 3) << 2;     // 0,4,8,12

    float acc[4][4];
    #pragma unroll
    for (int i = 0; i < 4; ++i)
        #pragma unroll
        for (int j = 0; j < 4; ++j) acc[i][j] = 0.f;

    for (int k0 = 0; k0 < K; k0 += 16) {
        float4 av = *(const float4*)(A + (size_t)(m0 + lm) * K + k0 + lk);
        float4 wv = *(const float4*)(W + (size_t)(n0 + lm) * K + k0 + lk);
        As[lk+0][lm] = av.x; As[lk+1][lm] = av.y; As[lk+2][lm] = av.z; As[lk+3][lm] = av.w;
        Ws[lk+0][lm] = wv.x; Ws[lk+1][lm] = wv.y; Ws[lk+2][lm] = wv.z; Ws[lk+3][lm] = wv.w;
        __syncthreads();
        #pragma unroll
        for (int kk = 0; kk < 16; ++kk) {
            float4 a4 = *(const float4*)&As[kk][ty * 4];
            float4 b4 = *(const float4*)&Ws[kk][tx * 4];
            float aa[4] = {a4.x, a4.y, a4.z, a4.w};
            float bb[4] = {b4.x, b4.y, b4.z, b4.w};
            #pragma unroll
            for (int i = 0; i < 4; ++i)
                #pragma unroll
                for (int j = 0; j < 4; ++j)
                    acc[i][j] += aa[i] * bb[j];
        }
        __syncthreads();
    }

    float4 bv = *(const float4*)(bias + n0 + tx * 4);
    #pragma unroll
    for (int i = 0; i < 4; ++i) {
        float4 o;
        o.x = acc[i][0] + bv.x;
        o.y = acc[i][1] + bv.y;
        o.z = acc[i][2] + bv.z;
        o.w = acc[i][3] + bv.w;
        *(float4*)(C + (size_t)(m0 + ty * 4 + i) * N + n0 + tx * 4) = o;
    }
}

// ---------------------------------------------------------------------------
// Fused attention: one block handles TQ=4 query rows of one batch.
// Per head: scores -> softmax (exact) -> accumulate sum/mask (registers) ->
// masked probs @ V -> merged ctx. Writes sum/mask once at the end.
// ---------------------------------------------------------------------------
__global__ __launch_bounds__(256) void attn_kernel(
    const float* __restrict__ Q, const float* __restrict__ K,
    const float* __restrict__ V, float* __restrict__ merged,
    float* __restrict__ osum, float* __restrict__ omask)
{
    extern __shared__ float sm[];
    float* sm_q   = sm;                 // TQ*Dd   = 4096 floats
    float* sm_s   = sm + TQ * Dd;       // TQ*Ss   = 8192 floats
    float* sm_red = sm_s + TQ * Ss;     // 4096 floats (reductions / ctx partials)

    const int tid = threadIdx.x;
    const int b  = blockIdx.x / (Ss / TQ);
    const int q0 = (blockIdx.x % (Ss / TQ)) * TQ;

    const float* Qb = Q + ((size_t)b * Ss + q0) * Dd;
    const float* Kb = K + (size_t)b * Ss * Dd;
    const float* Vb = V + (size_t)b * Ss * Dd;

    for (int i = tid; i < TQ * Dd; i += 256) sm_q[i] = Qb[i];

    float psum[TQ][8], pmask[TQ][8];
    #pragma unroll
    for (int q = 0; q < TQ; ++q)
        #pragma unroll
        for (int i = 0; i < 8; ++i) { psum[q][i] = 0.f; pmask[q][i] = 0.f; }

    const int d4 = tid & 15;   // float4 index within head dim (16*4 = 64)
    const int ks = tid >> 4;   // 0..15 k-strip

    __syncthreads();

    for (int h = 0; h < Hh; ++h) {
        const int hd = h * DKk;

        // ---- scores = (q . k) / sqrt(64) ----
        for (int k = tid; k < Ss; k += 256) {
            const float4* kr = (const float4*)(Kb + (size_t)k * Dd + hd);
            float acc[TQ] = {0.f, 0.f, 0.f, 0.f};
            #pragma unroll
            for (int dd = 0; dd < DKk / 4; ++dd) {
                float4 kv = kr[dd];
                #pragma unroll
                for (int q = 0; q < TQ; ++q) {
                    float4 qv = ((const float4*)(sm_q + q * Dd + hd))[dd];
                    acc[q] += qv.x * kv.x + qv.y * kv.y + qv.z * kv.z + qv.w * kv.w;
                }
            }
            #pragma unroll
            for (int q = 0; q < TQ; ++q) sm_s[q * Ss + k] = acc[q] * 0.125f;
        }
        __syncthreads();

        // ---- row max ----
        float mx[TQ];
        #pragma unroll
        for (int q = 0; q < TQ; ++q) mx[q] = -1e30f;
        for (int k = tid; k < Ss; k += 256)
            #pragma unroll
            for (int q = 0; q < TQ; ++q) mx[q] = fmaxf(mx[q], sm_s[q * Ss + k]);
        #pragma unroll
        for (int q = 0; q < TQ; ++q) sm_red[q * 256 + tid] = mx[q];
        __syncthreads();
        for (int off = 128; off > 0; off >>= 1) {
            if (tid < off)
                #pragma unroll
                for (int q = 0; q < TQ; ++q)
                    sm_red[q * 256 + tid] = fmaxf(sm_red[q * 256 + tid],
                                                  sm_red[q * 256 + tid + off]);
            __syncthreads();
        }
        #pragma unroll
        for (int q = 0; q < TQ; ++q) mx[q] = sm_red[q * 256];
        __syncthreads();

        // ---- exp & row sum ----
        float sums[TQ] = {0.f, 0.f, 0.f, 0.f};
        for (int k = tid; k < Ss; k += 256)
            #pragma unroll
            for (int q = 0; q < TQ; ++q) {
                float e = expf(sm_s[q * Ss + k] - mx[q]);
                sm_s[q * Ss + k] = e;
                sums[q] += e;
            }
        #pragma unroll
        for (int q = 0; q < TQ; ++q) sm_red[q * 256 + tid] = sums[q];
        __syncthreads();
        for (int off = 128; off > 0; off >>= 1) {
            if (tid < off)
                #pragma unroll
                for (int q = 0; q < TQ; ++q)
                    sm_red[q * 256 + tid] += sm_red[q * 256 + tid + off];
            __syncthreads();
        }
        float inv[TQ];
        #pragma unroll
        for (int q = 0; q < TQ; ++q) inv[q] = 1.0f / sm_red[q * 256];
        __syncthreads();

        // ---- normalize, accumulate sum/mask (regs), write masked probs ----
        #pragma unroll
        for (int i = 0; i < 8; ++i) {
            int k = tid + 256 * i;
            #pragma unroll
            for (int q = 0; q < TQ; ++q) {
                float p = sm_s[q * Ss + k] * inv[q];
                float keep = (p >= TH) ? 1.0f : 0.0f;
                psum[q][i]  += p;
                pmask[q][i] += keep;
                sm_s[q * Ss + k] = keep * p;
            }
        }
        __syncthreads();

        // ---- ctx = probs_masked @ V (this head's 64 dims) ----
        float4 ctx[TQ];
        #pragma unroll
        for (int q = 0; q < TQ; ++q) ctx[q] = make_float4(0.f, 0.f, 0.f, 0.f);
        for (int k = ks; k < Ss; k += 16) {
            float4 vv = *(const float4*)(Vb + (size_t)k * Dd + hd + d4 * 4);
            #pragma unroll
            for (int q = 0; q < TQ; ++q) {
                float p = sm_s[q * Ss + k];
                ctx[q].x += p * vv.x; ctx[q].y += p * vv.y;
                ctx[q].z += p * vv.z; ctx[q].w += p * vv.w;
            }
        }
        float4* red4 = (float4*)sm_red;
        #pragma unroll
        for (int q = 0; q < TQ; ++q) red4[(q * 16 + ks) * 16 + d4] = ctx[q];
        __syncthreads();
        if (tid < 64) {
            int q = tid >> 4, dd = tid & 15;
            float4 a = make_float4(0.f, 0.f, 0.f, 0.f);
            #pragma unroll
            for (int s = 0; s < 16; ++s) {
                float4 t = red4[(q * 16 + s) * 16 + dd];
                a.x += t.x; a.y += t.y; a.z += t.z; a.w += t.w;
            }
            *(float4*)(merged + ((size_t)b * Ss + q0 + q) * Dd + hd + dd * 4) = a;
        }
        __syncthreads();
    }

    // ---- write attention_sum / attention_mask ----
    #pragma unroll
    for (int i = 0; i < 8; ++i) {
        int k = tid + 256 * i;
        #pragma unroll
        for (int q = 0; q < TQ; ++q) {
            size_t row = (size_t)b * Ss + q0 + q;
            osum [row * Ss + k] = psum[q][i];
            omask[row * Ss + k] = pmask[q][i];
        }
    }
}

extern "C" void kernel_launch(void* const* d_in, const int* in_sizes, int n_in,
                              void* d_out, int out_size)
{
    const float* x  = (const float*)d_in[0];
    const float* Wq = (const float*)d_in[1];
    const float* bq = (const float*)d_in[2];
    const float* Wk = (const float*)d_in[3];
    const float* bk = (const float*)d_in[4];
    const float* Wv = (const float*)d_in[5];
    const float* bv = (const float*)d_in[6];
    const float* Wo = (const float*)d_in[7];
    const float* bo = (const float*)d_in[8];

    float* out   = (float*)d_out;                       // [B,S,D]
    float* osum  = out  + (size_t)Bb * Ss * Dd;         // [B,S,S]
    float* omask = osum + (size_t)Bb * Ss * Ss;         // [B,S,S]

    float *q, *k, *v, *m;
    cudaGetSymbolAddress((void**)&q, g_q);
    cudaGetSymbolAddress((void**)&k, g_k);
    cudaGetSymbolAddress((void**)&v, g_v);
    cudaGetSymbolAddress((void**)&m, g_m);

    const int Mrows = Bb * Ss;                          // 4096
    dim3 gg(Dd / 64, Mrows / 64);                       // (16, 64)
    gemm_bias<<<gg, 256>>>(x, Wq, bq, q, Mrows, Dd, Dd);
    gemm_bias<<<gg, 256>>>(x, Wk, bk, k, Mrows, Dd, Dd);
    gemm_bias<<<gg, 256>>>(x, Wv, bv, v, Mrows, Dd, Dd);

    size_t smem = (size_t)(TQ * Dd + TQ * Ss + 4096) * sizeof(float);  // 64 KB
    cudaFuncSetAttribute(attn_kernel, cudaFuncAttributeMaxDynamicSharedMemorySize,
                         (int)smem);
    attn_kernel<<<Bb * Ss / TQ, 256, smem>>>(q, k, v, m, osum, omask);

    gemm_bias<<<gg, 256>>>(m, Wo, bo, out, Mrows, Dd, Dd);
}

// round 2
// speedup vs baseline: 2.0046x; 2.0046x over previous
#include <cuda_runtime.h>
#include <math.h>

#define Bb 2
#define Ss 2048
#define Dd 1024
#define Hh 16
#define DKk 64
#define TQ 8
#define NT 512
#define TH 0.1f

// Scratch (allocation-free rule: __device__ globals)
__device__ float g_q [Bb*Ss*Dd];
__device__ float g_k [Bb*Ss*Dd];
__device__ float g_v [Bb*Ss*Dd];
__device__ float g_m [Bb*Ss*Dd];
__device__ float g_kt[Bb*Ss*Dd];   // KT[(b*H+h)*64 + d][s]

// ---------------------------------------------------------------------------
// fast exp: x <= ~0, FMA-pipe only (no MUFU). |rel err| < 1e-8.
// ---------------------------------------------------------------------------
__device__ __forceinline__ float fexp(float x) {
    x = fmaxf(x, -87.0f);
    float p = x * 1.44269504088896340f;
    int   ni = __float2int_rn(p);
    float f  = p - (float)ni;
    float t  = f * 0.69314718055994531f;
    float r  = 1.9841269841269841e-4f;          // 1/5040
    r = fmaf(r, t, 1.3888888888888889e-3f);     // 1/720
    r = fmaf(r, t, 8.3333333333333333e-3f);     // 1/120
    r = fmaf(r, t, 4.1666666666666664e-2f);     // 1/24
    r = fmaf(r, t, 1.6666666666666666e-1f);     // 1/6
    r = fmaf(r, t, 0.5f);
    r = fmaf(r, t, 1.0f);
    r = fmaf(r, t, 1.0f);
    float sc = __int_as_float((ni + 127) << 23);
    return r * sc;
}

// ---------------------------------------------------------------------------
// C[M,N] = A[M,K] @ W[N,K]^T + bias
// ---------------------------------------------------------------------------
__global__ __launch_bounds__(256) void gemm_bias(
    const float* __restrict__ A, const float* __restrict__ W,
    const float* __restrict__ bias, float* __restrict__ C,
    int M, int N, int K)
{
    __shared__ float As[16][68];
    __shared__ float Ws[16][68];
    const int tid = threadIdx.x;
    const int tx = tid & 15, ty = tid >> 4;
    const int m0 = blockIdx.y * 64, n0 = blockIdx.x * 64;
    const int lm = tid >> 2;
    const int lk = (tid & 3) << 2;

    float acc[4][4];
    #pragma unroll
    for (int i = 0; i < 4; ++i)
        #pragma unroll
        for (int j = 0; j < 4; ++j) acc[i][j] = 0.f;

    for (int k0 = 0; k0 < K; k0 += 16) {
        float4 av = *(const float4*)(A + (size_t)(m0 + lm) * K + k0 + lk);
        float4 wv = *(const float4*)(W + (size_t)(n0 + lm) * K + k0 + lk);
        As[lk+0][lm] = av.x; As[lk+1][lm] = av.y; As[lk+2][lm] = av.z; As[lk+3][lm] = av.w;
        Ws[lk+0][lm] = wv.x; Ws[lk+1][lm] = wv.y; Ws[lk+2][lm] = wv.z; Ws[lk+3][lm] = wv.w;
        __syncthreads();
        #pragma unroll
        for (int kk = 0; kk < 16; ++kk) {
            float4 a4 = *(const float4*)&As[kk][ty * 4];
            float4 b4 = *(const float4*)&Ws[kk][tx * 4];
            float aa[4] = {a4.x, a4.y, a4.z, a4.w};
            float bb[4] = {b4.x, b4.y, b4.z, b4.w};
            #pragma unroll
            for (int i = 0; i < 4; ++i)
                #pragma unroll
                for (int j = 0; j < 4; ++j)
                    acc[i][j] += aa[i] * bb[j];
        }
        __syncthreads();
    }

    float4 bv = *(const float4*)(bias + n0 + tx * 4);
    #pragma unroll
    for (int i = 0; i < 4; ++i) {
        float4 o;
        o.x = acc[i][0] + bv.x;
        o.y = acc[i][1] + bv.y;
        o.z = acc[i][2] + bv.z;
        o.w = acc[i][3] + bv.w;
        *(float4*)(C + (size_t)(m0 + ty * 4 + i) * N + n0 + tx * 4) = o;
    }
}

// ---------------------------------------------------------------------------
// Transpose K[b, s, c] -> KT[b*1024 + c][s]   (c = h*64+d)
// ---------------------------------------------------------------------------
__global__ __launch_bounds__(256) void transpose_k(
    const float* __restrict__ k, float* __restrict__ kt)
{
    __shared__ float t[32][33];
    const int tx = threadIdx.x, ty = threadIdx.y;       // 32 x 8
    const int s0 = blockIdx.x * 32;
    const int c0 = blockIdx.y * 32;
    const int b  = blockIdx.z;
    const float* src = k  + (size_t)b * Ss * Dd;
    float*       dst = kt + (size_t)b * Dd * Ss;
    #pragma unroll
    for (int r = 0; r < 4; ++r)
        t[ty + 8*r][tx] = src[(size_t)(s0 + ty + 8*r) * Dd + c0 + tx];
    __syncthreads();
    #pragma unroll
    for (int r = 0; r < 4; ++r)
        dst[(size_t)(c0 + ty + 8*r) * Ss + s0 + tx] = t[tx][ty + 8*r];
}

// ---------------------------------------------------------------------------
// Fused attention: TQ=8 query rows / block, 512 threads.
// sm layout: q[8192] | s[16384] | red[8192]  = 128 KB
// ---------------------------------------------------------------------------
__global__ __launch_bounds__(NT) void attn_kernel(
    const float* __restrict__ Q, const float* __restrict__ KT,
    const float* __restrict__ V, float* __restrict__ merged,
    float* __restrict__ osum, float* __restrict__ omask)
{
    extern __shared__ float sm[];
    float* sm_q   = sm;                  // 8192
    float* sm_s   = sm + TQ * Dd;        // 16384
    float* sm_red = sm_s + TQ * Ss;      // 8192

    const int tid  = threadIdx.x;
    const int lane = tid & 31;
    const int wid  = tid >> 5;           // 0..15
    const int b    = blockIdx.x >> 8;    // 512 blocks: 2 x 256
    const int q0   = (blockIdx.x & 255) * TQ;
    const int k0   = tid * 4;            // this thread's float4 k-slot

    const float* Qb  = Q  + ((size_t)b * Ss + q0) * Dd;
    const float* KTb = KT + (size_t)b * Dd * Ss;
    const float* Vb  = V  + (size_t)b * Ss * Dd;

    // load q rows
    #pragma unroll
    for (int i = 0; i < TQ * Dd / (NT * 4); ++i)
        ((float4*)sm_q)[tid + i * NT] = ((const float4*)Qb)[tid + i * NT];

    float4 psum[TQ], pmask[TQ];
    #pragma unroll
    for (int q = 0; q < TQ; ++q) {
        psum[q]  = make_float4(0.f, 0.f, 0.f, 0.f);
        pmask[q] = make_float4(0.f, 0.f, 0.f, 0.f);
    }

    const int d2 = tid & 31;             // float2 lane within head dim
    const int ks = tid >> 5;             // k strip 0..15

    __syncthreads();

    for (int h = 0; h < Hh; ++h) {
        const int hd = h * DKk;
        const float* kt = KTb + (size_t)hd * Ss;

        // ---- scores (coalesced KT loads) + local max ----
        float4 acc[TQ];
        #pragma unroll
        for (int q = 0; q < TQ; ++q) acc[q] = make_float4(0.f, 0.f, 0.f, 0.f);
        #pragma unroll 4
        for (int d = 0; d < DKk; ++d) {
            float4 kv = *(const float4*)(kt + (size_t)d * Ss + k0);
            #pragma unroll
            for (int q = 0; q < TQ; ++q) {
                float qv = sm_q[q * Dd + hd + d];
                acc[q].x = fmaf(qv, kv.x, acc[q].x);
                acc[q].y = fmaf(qv, kv.y, acc[q].y);
                acc[q].z = fmaf(qv, kv.z, acc[q].z);
                acc[q].w = fmaf(qv, kv.w, acc[q].w);
            }
        }
        float mx[TQ];
        #pragma unroll
        for (int q = 0; q < TQ; ++q) {
            acc[q].x *= 0.125f; acc[q].y *= 0.125f;
            acc[q].z *= 0.125f; acc[q].w *= 0.125f;
            ((float4*)(sm_s + q * Ss))[tid] = acc[q];
            mx[q] = fmaxf(fmaxf(acc[q].x, acc[q].y), fmaxf(acc[q].z, acc[q].w));
        }

        // ---- block max ----
        #pragma unroll
        for (int q = 0; q < TQ; ++q) {
            #pragma unroll
            for (int off = 16; off > 0; off >>= 1)
                mx[q] = fmaxf(mx[q], __shfl_xor_sync(0xffffffffu, mx[q], off));
            if (lane == 0) sm_red[q * 16 + wid] = mx[q];
        }
        __syncthreads();
        if (wid < TQ && lane < 16) {
            float v = sm_red[wid * 16 + lane];
            #pragma unroll
            for (int off = 8; off > 0; off >>= 1)
                v = fmaxf(v, __shfl_xor_sync(0xffffu, v, off));
            if (lane == 0) sm_red[wid * 16] = v;
        }
        __syncthreads();
        float mxf[TQ];
        #pragma unroll
        for (int q = 0; q < TQ; ++q) mxf[q] = sm_red[q * 16];

        // ---- exp + local sum ----
        float sums[TQ];
        #pragma unroll
        for (int q = 0; q < TQ; ++q) {
            float4 s4 = ((float4*)(sm_s + q * Ss))[tid];
            s4.x = fexp(s4.x - mxf[q]); s4.y = fexp(s4.y - mxf[q]);
            s4.z = fexp(s4.z - mxf[q]); s4.w = fexp(s4.w - mxf[q]);
            ((float4*)(sm_s + q * Ss))[tid] = s4;
            sums[q] = (s4.x + s4.y) + (s4.z + s4.w);
        }
        __syncthreads();   // protect sm_red (mxf) before reuse

        // ---- block sum ----
        #pragma unroll
        for (int q = 0; q < TQ; ++q) {
            #pragma unroll
            for (int off = 16; off > 0; off >>= 1)
                sums[q] += __shfl_xor_sync(0xffffffffu, sums[q], off);
            if (lane == 0) sm_red[q * 16 + wid] = sums[q];
        }
        __syncthreads();
        if (wid < TQ && lane < 16) {
            float v = sm_red[wid * 16 + lane];
            #pragma unroll
            for (int off = 8; off > 0; off >>= 1)
                v += __shfl_xor_sync(0xffffu, v, off);
            if (lane == 0) sm_red[wid * 16] = v;
        }
        __syncthreads();
        float invf[TQ];
        #pragma unroll
        for (int q = 0; q < TQ; ++q) invf[q] = 1.0f / sm_red[q * 16];

        // ---- normalize + mask + accumulate head sums ----
        #pragma unroll
        for (int q = 0; q < TQ; ++q) {
            float4 e4 = ((float4*)(sm_s + q * Ss))[tid];
            float4 p4;
            p4.x = e4.x * invf[q]; p4.y = e4.y * invf[q];
            p4.z = e4.z * invf[q]; p4.w = e4.w * invf[q];
            float4 kp;
            kp.x = (p4.x >= TH) ? 1.f : 0.f; kp.y = (p4.y >= TH) ? 1.f : 0.f;
            kp.z = (p4.z >= TH) ? 1.f : 0.f; kp.w = (p4.w >= TH) ? 1.f : 0.f;
            psum[q].x += p4.x; psum[q].y += p4.y;
            psum[q].z += p4.z; psum[q].w += p4.w;
            pmask[q].x += kp.x; pmask[q].y += kp.y;
            pmask[q].z += kp.z; pmask[q].w += kp.w;
            float4 mp;
            mp.x = kp.x * p4.x; mp.y = kp.y * p4.y;
            mp.z = kp.z * p4.z; mp.w = kp.w * p4.w;
            ((float4*)(sm_s + q * Ss))[tid] = mp;
        }
        __syncthreads();

        // ---- PV: ctx[q] (float2 per thread), V read once per block ----
        float2 ctx[TQ];
        #pragma unroll
        for (int q = 0; q < TQ; ++q) ctx[q] = make_float2(0.f, 0.f);
        const float* vb = Vb + hd + d2 * 2;
        #pragma unroll 4
        for (int i = 0; i < Ss / 16; ++i) {
            int k = ks + 16 * i;
            float2 vv = *(const float2*)(vb + (size_t)k * Dd);
            #pragma unroll
            for (int q = 0; q < TQ; ++q) {
                float p = sm_s[q * Ss + k];
                ctx[q].x = fmaf(p, vv.x, ctx[q].x);
                ctx[q].y = fmaf(p, vv.y, ctx[q].y);
            }
        }
        float2* red2 = (float2*)sm_red;
        #pragma unroll
        for (int q = 0; q < TQ; ++q)
            red2[(q * 16 + ks) * 32 + d2] = ctx[q];
        __syncthreads();
        if (tid < 256) {
            int q = tid >> 5, dl = tid & 31;
            float2 a = make_float2(0.f, 0.f);
            #pragma unroll
            for (int s = 0; s < 16; ++s) {
                float2 t = red2[(q * 16 + s) * 32 + dl];
                a.x += t.x; a.y += t.y;
            }
            *(float2*)(merged + ((size_t)b * Ss + q0 + q) * Dd + hd + dl * 2) = a;
        }
        __syncthreads();
    }

    // ---- write attention_sum / attention_mask (float4, coalesced) ----
    #pragma unroll
    for (int q = 0; q < TQ; ++q) {
        size_t row = (size_t)b * Ss + q0 + q;
        ((float4*)(osum  + row * Ss))[tid] = psum[q];
        ((float4*)(omask + row * Ss))[tid] = pmask[q];
    }
}

extern "C" void kernel_launch(void* const* d_in, const int* in_sizes, int n_in,
                              void* d_out, int out_size)
{
    const float* x  = (const float*)d_in[0];
    const float* Wq = (const float*)d_in[1];
    const float* bq = (const float*)d_in[2];
    const float* Wk = (const float*)d_in[3];
    const float* bk = (const float*)d_in[4];
    const float* Wv = (const float*)d_in[5];
    const float* bv = (const float*)d_in[6];
    const float* Wo = (const float*)d_in[7];
    const float* bo = (const float*)d_in[8];

    float* out   = (float*)d_out;
    float* osum  = out  + (size_t)Bb * Ss * Dd;
    float* omask = osum + (size_t)Bb * Ss * Ss;

    float *q, *k, *v, *m, *kt;
    cudaGetSymbolAddress((void**)&q,  g_q);
    cudaGetSymbolAddress((void**)&k,  g_k);
    cudaGetSymbolAddress((void**)&v,  g_v);
    cudaGetSymbolAddress((void**)&m,  g_m);
    cudaGetSymbolAddress((void**)&kt, g_kt);

    const int Mrows = Bb * Ss;
    dim3 gg(Dd / 64, Mrows / 64);
    gemm_bias<<<gg, 256>>>(x, Wq, bq, q, Mrows, Dd, Dd);
    gemm_bias<<<gg, 256>>>(x, Wk, bk, k, Mrows, Dd, Dd);
    gemm_bias<<<gg, 256>>>(x, Wv, bv, v, Mrows, Dd, Dd);

    transpose_k<<<dim3(Ss / 32, Dd / 32, Bb), dim3(32, 8)>>>(k, kt);

    size_t smem = (size_t)(TQ * Dd + TQ * Ss + 8192) * sizeof(float);  // 128 KB
    cudaFuncSetAttribute(attn_kernel, cudaFuncAttributeMaxDynamicSharedMemorySize,
                         (int)smem);
    attn_kernel<<<Bb * Ss / TQ, NT, smem>>>(q, kt, v, m, osum, omask);

    gemm_bias<<<gg, 256>>>(m, Wo, bo, out, Mrows, Dd, Dd);
}

// round 5
// speedup vs baseline: 2.4625x; 1.2284x over previous
#include <cuda_runtime.h>
#include <cuda_bf16.h>
#include <cstdint>
#include <math.h>

#define Bb 2
#define Ss 2048
#define Dd 1024
#define Hh 16
#define DKk 64
#define TQ 8
#define NT 512
#define TH 0.1f

// ---------------- scratch (__device__ globals; no allocs allowed) ----------
__device__ float g_q [Bb*Ss*Dd];
__device__ float g_k [Bb*Ss*Dd];
__device__ float g_v [Bb*Ss*Dd];
__device__ float g_m [Bb*Ss*Dd];
__device__ float g_kt[Bb*Ss*Dd];
__device__ __nv_bfloat16 g_xhi[Bb*Ss*Dd], g_xlo[Bb*Ss*Dd];
__device__ __nv_bfloat16 g_mhi[Bb*Ss*Dd], g_mlo[Bb*Ss*Dd];
__device__ __nv_bfloat16 g_whi[4*Dd*Dd],  g_wlo[4*Dd*Dd];

// one dynamic-shared symbol for the whole TU
extern __shared__ char smraw[];

// ---------------- mma.sync helpers (base ISA, works on compute_103) --------
__device__ __forceinline__ uint32_t smem_u32(const void* p) {
    uint32_t a;
    asm("{ .reg .u64 t; cvta.to.shared.u64 t, %1; cvt.u32.u64 %0, t; }" : "=r"(a) : "l"(p));
    return a;
}
__device__ __forceinline__ void ldsm_x4(uint32_t& r0, uint32_t& r1, uint32_t& r2,
                                        uint32_t& r3, uint32_t addr) {
    asm volatile("ldmatrix.sync.aligned.m8n8.x4.shared.b16 {%0,%1,%2,%3}, [%4];"
                 : "=r"(r0), "=r"(r1), "=r"(r2), "=r"(r3) : "r"(addr));
}
__device__ __forceinline__ void ldsm_x2(uint32_t& r0, uint32_t& r1, uint32_t addr) {
    asm volatile("ldmatrix.sync.aligned.m8n8.x2.shared.b16 {%0,%1}, [%2];"
                 : "=r"(r0), "=r"(r1) : "r"(addr));
}
__device__ __forceinline__ void mma_bf16(float* d, const uint32_t* a, const uint32_t* b) {
    asm volatile(
        "mma.sync.aligned.m16n8k16.row.col.f32.bf16.bf16.f32 "
        "{%0,%1,%2,%3}, {%4,%5,%6,%7}, {%8,%9}, {%0,%1,%2,%3};"
        : "+f"(d[0]), "+f"(d[1]), "+f"(d[2]), "+f"(d[3])
        : "r"(a[0]), "r"(a[1]), "r"(a[2]), "r"(a[3]), "r"(b[0]), "r"(b[1]));
}

// ---------------------------------------------------------------------------
// split fp32 -> bf16 hi + bf16 lo
// ---------------------------------------------------------------------------
__global__ __launch_bounds__(256) void split4(
    const float4* __restrict__ x, __nv_bfloat162* __restrict__ hi,
    __nv_bfloat162* __restrict__ lo, int n4)
{
    int i = blockIdx.x * 256 + threadIdx.x;
    if (i >= n4) return;
    float4 v = x[i];
    __nv_bfloat16 hx = __float2bfloat16(v.x);
    __nv_bfloat16 hy = __float2bfloat16(v.y);
    __nv_bfloat16 hz = __float2bfloat16(v.z);
    __nv_bfloat16 hw = __float2bfloat16(v.w);
    __nv_bfloat16 lx = __float2bfloat16(v.x - __bfloat162float(hx));
    __nv_bfloat16 ly = __float2bfloat16(v.y - __bfloat162float(hy));
    __nv_bfloat16 lz = __float2bfloat16(v.z - __bfloat162float(hz));
    __nv_bfloat16 lw = __float2bfloat16(v.w - __bfloat162float(hw));
    hi[2*i]   = __halves2bfloat162(hx, hy);
    hi[2*i+1] = __halves2bfloat162(hz, hw);
    lo[2*i]   = __halves2bfloat162(lx, ly);
    lo[2*i+1] = __halves2bfloat162(lz, lw);
}

// ---------------------------------------------------------------------------
// HMMA GEMM: C[M,N] = A[M,K] @ W[N,K]^T + bias, fp32-accurate bf16 split
// (hi*hi + hi*lo + lo*hi).  CTA tile 128x128, K-chunk 32, 8 warps (64x32 each),
// m16n8k16 tiles, smem rows padded to 40 bf16 for conflict-free ldmatrix.
// ---------------------------------------------------------------------------
#define SROW 40
#define S_AH 0
#define S_AL (128*SROW)
#define S_BH (2*128*SROW)
#define S_BL (3*128*SROW)

__global__ __launch_bounds__(256, 1)
void gemm_mma(const __nv_bfloat16* __restrict__ Ahi, const __nv_bfloat16* __restrict__ Alo,
              const __nv_bfloat16* __restrict__ Whi, const __nv_bfloat16* __restrict__ Wlo,
              const float* __restrict__ bias, float* __restrict__ C,
              int Kdim, int Ndim)
{
    __nv_bfloat16* sb = (__nv_bfloat16*)smraw;
    const uint32_t sbase = smem_u32(sb);
    const int tid = threadIdx.x, lane = tid & 31, wid = tid >> 5;
    const int wm = (wid >> 2) * 64;        // warp m offset (0/64)
    const int wn = (wid & 3) * 32;         // warp n offset (0/32/64/96)
    const int n0 = blockIdx.x * 128, m0 = blockIdx.y * 128;

    // ldmatrix lane address offsets (bytes) within each smem array
    uint32_t aoff[4], boff[4];
    #pragma unroll
    for (int mt = 0; mt < 4; ++mt)
        aoff[mt] = ((wm + mt * 16 + (lane & 15)) * SROW + (lane >> 4) * 8) * 2;
    #pragma unroll
    for (int nt = 0; nt < 4; ++nt)
        boff[nt] = ((wn + nt * 8 + (lane & 7)) * SROW + ((lane >> 3) & 1) * 8) * 2;

    // gmem->smem slot mapping: 512 uint4 per array, 2 per thread
    const int s0 = tid, s1 = tid + 256;
    const int r0 = s0 >> 2, c0 = (s0 & 3) * 8;
    const int r1 = s1 >> 2, c1 = (s1 & 3) * 8;

    float d[4][4][4];
    #pragma unroll
    for (int mt = 0; mt < 4; ++mt)
        #pragma unroll
        for (int nt = 0; nt < 4; ++nt)
            #pragma unroll
            for (int i = 0; i < 4; ++i) d[mt][nt][i] = 0.f;

    const int nkt = Kdim >> 5;   // 32-wide K chunks
    // prefetch chunk 0
    uint4 pah0, pah1, pal0, pal1, pbh0, pbh1, pbl0, pbl1;
    {
        const int kb = 0;
        pah0 = *(const uint4*)(Ahi + (size_t)(m0 + r0) * Kdim + kb + c0);
        pah1 = *(const uint4*)(Ahi + (size_t)(m0 + r1) * Kdim + kb + c1);
        pal0 = *(const uint4*)(Alo + (size_t)(m0 + r0) * Kdim + kb + c0);
        pal1 = *(const uint4*)(Alo + (size_t)(m0 + r1) * Kdim + kb + c1);
        pbh0 = *(const uint4*)(Whi + (size_t)(n0 + r0) * Kdim + kb + c0);
        pbh1 = *(const uint4*)(Whi + (size_t)(n0 + r1) * Kdim + kb + c1);
        pbl0 = *(const uint4*)(Wlo + (size_t)(n0 + r0) * Kdim + kb + c0);
        pbl1 = *(const uint4*)(Wlo + (size_t)(n0 + r1) * Kdim + kb + c1);
    }

    for (int kt = 0; kt < nkt; ++kt) {
        // store prefetched chunk to smem
        *(uint4*)(sb + S_AH + r0 * SROW + c0) = pah0;
        *(uint4*)(sb + S_AH + r1 * SROW + c1) = pah1;
        *(uint4*)(sb + S_AL + r0 * SROW + c0) = pal0;
        *(uint4*)(sb + S_AL + r1 * SROW + c1) = pal1;
        *(uint4*)(sb + S_BH + r0 * SROW + c0) = pbh0;
        *(uint4*)(sb + S_BH + r1 * SROW + c1) = pbh1;
        *(uint4*)(sb + S_BL + r0 * SROW + c0) = pbl0;
        *(uint4*)(sb + S_BL + r1 * SROW + c1) = pbl1;
        __syncthreads();

        // prefetch next chunk (latency hidden by MMA work below)
        if (kt + 1 < nkt) {
            const int kb = (kt + 1) << 5;
            pah0 = *(const uint4*)(Ahi + (size_t)(m0 + r0) * Kdim + kb + c0);
            pah1 = *(const uint4*)(Ahi + (size_t)(m0 + r1) * Kdim + kb + c1);
            pal0 = *(const uint4*)(Alo + (size_t)(m0 + r0) * Kdim + kb + c0);
            pal1 = *(const uint4*)(Alo + (size_t)(m0 + r1) * Kdim + kb + c1);
            pbh0 = *(const uint4*)(Whi + (size_t)(n0 + r0) * Kdim + kb + c0);
            pbh1 = *(const uint4*)(Whi + (size_t)(n0 + r1) * Kdim + kb + c1);
            pbl0 = *(const uint4*)(Wlo + (size_t)(n0 + r0) * Kdim + kb + c0);
            pbl1 = *(const uint4*)(Wlo + (size_t)(n0 + r1) * Kdim + kb + c1);
        }

        #pragma unroll
        for (int ks = 0; ks < 2; ++ks) {                 // two k16 steps
            const uint32_t kadd = ks * 32;               // 16 bf16 = 32 bytes
            uint32_t ah[4][4], al[4][4], bh[4][2], bl[4][2];
            #pragma unroll
            for (int mt = 0; mt < 4; ++mt) {
                ldsm_x4(ah[mt][0], ah[mt][1], ah[mt][2], ah[mt][3],
                        sbase + 2*S_AH + aoff[mt] + kadd);
                ldsm_x4(al[mt][0], al[mt][1], al[mt][2], al[mt][3],
                        sbase + 2*S_AL + aoff[mt] + kadd);
            }
            #pragma unroll
            for (int nt = 0; nt < 4; ++nt) {
                ldsm_x2(bh[nt][0], bh[nt][1], sbase + 2*S_BH + boff[nt] + kadd);
                ldsm_x2(bl[nt][0], bl[nt][1], sbase + 2*S_BL + boff[nt] + kadd);
            }
            #pragma unroll
            for (int mt = 0; mt < 4; ++mt)
                #pragma unroll
                for (int nt = 0; nt < 4; ++nt) {
                    mma_bf16(d[mt][nt], ah[mt], bh[nt]);
                    mma_bf16(d[mt][nt], ah[mt], bl[nt]);
                    mma_bf16(d[mt][nt], al[mt], bh[nt]);
                }
        }
        __syncthreads();
    }

    // epilogue: d0=(g,2c) d1=(g,2c+1) d2=(g+8,2c) d3=(g+8,2c+1)
    const int g = lane >> 2, c2 = (lane & 3) * 2;
    #pragma unroll
    for (int mt = 0; mt < 4; ++mt) {
        #pragma unroll
        for (int nt = 0; nt < 4; ++nt) {
            int m = m0 + wm + mt * 16 + g;
            int n = n0 + wn + nt * 8 + c2;
            float bx = bias[n], by = bias[n + 1];
            *(float2*)(C + (size_t)m * Ndim + n) =
                make_float2(d[mt][nt][0] + bx, d[mt][nt][1] + by);
            *(float2*)(C + (size_t)(m + 8) * Ndim + n) =
                make_float2(d[mt][nt][2] + bx, d[mt][nt][3] + by);
        }
    }
}

// ---------------------------------------------------------------------------
// fast exp (FMA pipe only)
// ---------------------------------------------------------------------------
__device__ __forceinline__ float fexp(float x) {
    x = fmaxf(x, -87.0f);
    float p = x * 1.44269504088896340f;
    int   ni = __float2int_rn(p);
    float f  = p - (float)ni;
    float t  = f * 0.69314718055994531f;
    float r  = 1.9841269841269841e-4f;
    r = fmaf(r, t, 1.3888888888888889e-3f);
    r = fmaf(r, t, 8.3333333333333333e-3f);
    r = fmaf(r, t, 4.1666666666666664e-2f);
    r = fmaf(r, t, 1.6666666666666666e-1f);
    r = fmaf(r, t, 0.5f);
    r = fmaf(r, t, 1.0f);
    r = fmaf(r, t, 1.0f);
    return r * __int_as_float((ni + 127) << 23);
}

// ---------------------------------------------------------------------------
// Transpose K[b,s,c] -> KT[b*1024+c][s]
// ---------------------------------------------------------------------------
__global__ __launch_bounds__(256) void transpose_k(
    const float* __restrict__ k, float* __restrict__ kt)
{
    __shared__ float t[32][33];
    const int tx = threadIdx.x, ty = threadIdx.y;
    const int s0 = blockIdx.x * 32, c0 = blockIdx.y * 32, b = blockIdx.z;
    const float* src = k  + (size_t)b * Ss * Dd;
    float*       dst = kt + (size_t)b * Dd * Ss;
    #pragma unroll
    for (int r = 0; r < 4; ++r)
        t[ty + 8*r][tx] = src[(size_t)(s0 + ty + 8*r) * Dd + c0 + tx];
    __syncthreads();
    #pragma unroll
    for (int r = 0; r < 4; ++r)
        dst[(size_t)(c0 + ty + 8*r) * Ss + s0 + tx] = t[tx][ty + 8*r];
}

// ---------------------------------------------------------------------------
// Fused attention: TQ=8 rows/block, 512 threads, 128KB smem
// ---------------------------------------------------------------------------
__global__ __launch_bounds__(NT) void attn_kernel(
    const float* __restrict__ Q, const float* __restrict__ KT,
    const float* __restrict__ V, float* __restrict__ merged,
    float* __restrict__ osum, float* __restrict__ omask)
{
    float* sm = (float*)smraw;
    float* sm_q   = sm;
    float* sm_s   = sm + TQ * Dd;
    float* sm_red = sm_s + TQ * Ss;

    const int tid  = threadIdx.x;
    const int lane = tid & 31;
    const int wid  = tid >> 5;
    const int b    = blockIdx.x >> 8;
    const int q0   = (blockIdx.x & 255) * TQ;
    const int k0   = tid * 4;

    const float* Qb  = Q  + ((size_t)b * Ss + q0) * Dd;
    const float* KTb = KT + (size_t)b * Dd * Ss;
    const float* Vb  = V  + (size_t)b * Ss * Dd;

    #pragma unroll
    for (int i = 0; i < TQ * Dd / (NT * 4); ++i)
        ((float4*)sm_q)[tid + i * NT] = ((const float4*)Qb)[tid + i * NT];

    float4 psum[TQ], pmask[TQ];
    #pragma unroll
    for (int q = 0; q < TQ; ++q) {
        psum[q]  = make_float4(0.f, 0.f, 0.f, 0.f);
        pmask[q] = make_float4(0.f, 0.f, 0.f, 0.f);
    }

    const int d2 = tid & 31;
    const int ks = tid >> 5;

    __syncthreads();

    for (int h = 0; h < Hh; ++h) {
        const int hd = h * DKk;
        const float* kt = KTb + (size_t)hd * Ss;

        float4 acc[TQ];
        #pragma unroll
        for (int q = 0; q < TQ; ++q) acc[q] = make_float4(0.f, 0.f, 0.f, 0.f);
        #pragma unroll 4
        for (int d = 0; d < DKk; ++d) {
            float4 kv = *(const float4*)(kt + (size_t)d * Ss + k0);
            #pragma unroll
            for (int q = 0; q < TQ; ++q) {
                float qv = sm_q[q * Dd + hd + d];
                acc[q].x = fmaf(qv, kv.x, acc[q].x);
                acc[q].y = fmaf(qv, kv.y, acc[q].y);
                acc[q].z = fmaf(qv, kv.z, acc[q].z);
                acc[q].w = fmaf(qv, kv.w, acc[q].w);
            }
        }
        float mx[TQ];
        #pragma unroll
        for (int q = 0; q < TQ; ++q) {
            acc[q].x *= 0.125f; acc[q].y *= 0.125f;
            acc[q].z *= 0.125f; acc[q].w *= 0.125f;
            ((float4*)(sm_s + q * Ss))[tid] = acc[q];
            mx[q] = fmaxf(fmaxf(acc[q].x, acc[q].y), fmaxf(acc[q].z, acc[q].w));
        }

        #pragma unroll
        for (int q = 0; q < TQ; ++q) {
            #pragma unroll
            for (int off = 16; off > 0; off >>= 1)
                mx[q] = fmaxf(mx[q], __shfl_xor_sync(0xffffffffu, mx[q], off));
            if (lane == 0) sm_red[q * 16 + wid] = mx[q];
        }
        __syncthreads();
        if (wid < TQ && lane < 16) {
            float v = sm_red[wid * 16 + lane];
            #pragma unroll
            for (int off = 8; off > 0; off >>= 1)
                v = fmaxf(v, __shfl_xor_sync(0xffffu, v, off));
            if (lane == 0) sm_red[wid * 16] = v;
        }
        __syncthreads();
        float mxf[TQ];
        #pragma unroll
        for (int q = 0; q < TQ; ++q) mxf[q] = sm_red[q * 16];

        float sums[TQ];
        #pragma unroll
        for (int q = 0; q < TQ; ++q) {
            float4 s4 = ((float4*)(sm_s + q * Ss))[tid];
            s4.x = fexp(s4.x - mxf[q]); s4.y = fexp(s4.y - mxf[q]);
            s4.z = fexp(s4.z - mxf[q]); s4.w = fexp(s4.w - mxf[q]);
            ((float4*)(sm_s + q * Ss))[tid] = s4;
            sums[q] = (s4.x + s4.y) + (s4.z + s4.w);
        }
        __syncthreads();

        #pragma unroll
        for (int q = 0; q < TQ; ++q) {
            #pragma unroll
            for (int off = 16; off > 0; off >>= 1)
                sums[q] += __shfl_xor_sync(0xffffffffu, sums[q], off);
            if (lane == 0) sm_red[q * 16 + wid] = sums[q];
        }
        __syncthreads();
        if (wid < TQ && lane < 16) {
            float v = sm_red[wid * 16 + lane];
            #pragma unroll
            for (int off = 8; off > 0; off >>= 1)
                v += __shfl_xor_sync(0xffffu, v, off);
            if (lane == 0) sm_red[wid * 16] = v;
        }
        __syncthreads();
        float invf[TQ];
        #pragma unroll
        for (int q = 0; q < TQ; ++q) invf[q] = 1.0f / sm_red[q * 16];

        #pragma unroll
        for (int q = 0; q < TQ; ++q) {
            float4 e4 = ((float4*)(sm_s + q * Ss))[tid];
            float4 p4;
            p4.x = e4.x * invf[q]; p4.y = e4.y * invf[q];
            p4.z = e4.z * invf[q]; p4.w = e4.w * invf[q];
            float4 kp;
            kp.x = (p4.x >= TH) ? 1.f : 0.f; kp.y = (p4.y >= TH) ? 1.f : 0.f;
            kp.z = (p4.z >= TH) ? 1.f : 0.f; kp.w = (p4.w >= TH) ? 1.f : 0.f;
            psum[q].x += p4.x; psum[q].y += p4.y;
            psum[q].z += p4.z; psum[q].w += p4.w;
            pmask[q].x += kp.x; pmask[q].y += kp.y;
            pmask[q].z += kp.z; pmask[q].w += kp.w;
            float4 mp;
            mp.x = kp.x * p4.x; mp.y = kp.y * p4.y;
            mp.z = kp.z * p4.z; mp.w = kp.w * p4.w;
            ((float4*)(sm_s + q * Ss))[tid] = mp;
        }
        __syncthreads();

        float2 ctx[TQ];
        #pragma unroll
        for (int q = 0; q < TQ; ++q) ctx[q] = make_float2(0.f, 0.f);
        const float* vb = Vb + hd + d2 * 2;
        #pragma unroll 4
        for (int i = 0; i < Ss / 16; ++i) {
            int k = ks + 16 * i;
            float2 vv = *(const float2*)(vb + (size_t)k * Dd);
            #pragma unroll
            for (int q = 0; q < TQ; ++q) {
                float p = sm_s[q * Ss + k];
                ctx[q].x = fmaf(p, vv.x, ctx[q].x);
                ctx[q].y = fmaf(p, vv.y, ctx[q].y);
            }
        }
        float2* red2 = (float2*)sm_red;
        #pragma unroll
        for (int q = 0; q < TQ; ++q)
            red2[(q * 16 + ks) * 32 + d2] = ctx[q];
        __syncthreads();
        if (tid < 256) {
            int q = tid >> 5, dl = tid & 31;
            float2 a = make_float2(0.f, 0.f);
            #pragma unroll
            for (int s = 0; s < 16; ++s) {
                float2 t = red2[(q * 16 + s) * 32 + dl];
                a.x += t.x; a.y += t.y;
            }
            *(float2*)(merged + ((size_t)b * Ss + q0 + q) * Dd + hd + dl * 2) = a;
        }
        __syncthreads();
    }

    #pragma unroll
    for (int q = 0; q < TQ; ++q) {
        size_t row = (size_t)b * Ss + q0 + q;
        ((float4*)(osum  + row * Ss))[tid] = psum[q];
        ((float4*)(omask + row * Ss))[tid] = pmask[q];
    }
}

// ---------------------------------------------------------------------------
extern "C" void kernel_launch(void* const* d_in, const int* in_sizes, int n_in,
                              void* d_out, int out_size)
{
    const float* x  = (const float*)d_in[0];
    const float* Wq = (const float*)d_in[1];
    const float* bq = (const float*)d_in[2];
    const float* Wk = (const float*)d_in[3];
    const float* bk = (const float*)d_in[4];
    const float* Wv = (const float*)d_in[5];
    const float* bv = (const float*)d_in[6];
    const float* Wo = (const float*)d_in[7];
    const float* bo = (const float*)d_in[8];

    float* out   = (float*)d_out;
    float* osum  = out  + (size_t)Bb * Ss * Dd;
    float* omask = osum + (size_t)Bb * Ss * Ss;

    float *q, *k, *v, *m, *kt;
    __nv_bfloat16 *xhi, *xlo, *mhi, *mlo, *whi, *wlo;
    cudaGetSymbolAddress((void**)&q,   g_q);
    cudaGetSymbolAddress((void**)&k,   g_k);
    cudaGetSymbolAddress((void**)&v,   g_v);
    cudaGetSymbolAddress((void**)&m,   g_m);
    cudaGetSymbolAddress((void**)&kt,  g_kt);
    cudaGetSymbolAddress((void**)&xhi, g_xhi);
    cudaGetSymbolAddress((void**)&xlo, g_xlo);
    cudaGetSymbolAddress((void**)&mhi, g_mhi);
    cudaGetSymbolAddress((void**)&mlo, g_mlo);
    cudaGetSymbolAddress((void**)&whi, g_whi);
    cudaGetSymbolAddress((void**)&wlo, g_wlo);

    const int NX = Bb * Ss * Dd;      // 4M
    const int NW = Dd * Dd;           // 1M

    // splits
    split4<<<NX/4/256, 256>>>((const float4*)x, (__nv_bfloat162*)xhi,
                              (__nv_bfloat162*)xlo, NX/4);
    const float* Wmats[4] = {Wq, Wk, Wv, Wo};
    for (int i = 0; i < 4; ++i)
        split4<<<NW/4/256, 256>>>((const float4*)Wmats[i],
                                  (__nv_bfloat162*)(whi + (size_t)i*NW),
                                  (__nv_bfloat162*)(wlo + (size_t)i*NW), NW/4);

    // HMMA GEMMs
    const size_t gsm = 4 * 128 * SROW * sizeof(__nv_bfloat16);   // 40960 B
    cudaFuncSetAttribute(gemm_mma, cudaFuncAttributeMaxDynamicSharedMemorySize, (int)gsm);
    dim3 gg(Dd / 128, Bb * Ss / 128);      // (8, 32)
    gemm_mma<<<gg, 256, gsm>>>(xhi, xlo, whi + 0*(size_t)NW, wlo + 0*(size_t)NW, bq, q, Dd, Dd);
    gemm_mma<<<gg, 256, gsm>>>(xhi, xlo, whi + 1*(size_t)NW, wlo + 1*(size_t)NW, bk, k, Dd, Dd);
    gemm_mma<<<gg, 256, gsm>>>(xhi, xlo, whi + 2*(size_t)NW, wlo + 2*(size_t)NW, bv, v, Dd, Dd);

    transpose_k<<<dim3(Ss / 32, Dd / 32, Bb), dim3(32, 8)>>>(k, kt);

    size_t asmem = (size_t)(TQ * Dd + TQ * Ss + 8192) * sizeof(float);  // 128 KB
    cudaFuncSetAttribute(attn_kernel, cudaFuncAttributeMaxDynamicSharedMemorySize, (int)asmem);
    attn_kernel<<<Bb * Ss / TQ, NT, asmem>>>(q, kt, v, m, osum, omask);

    split4<<<NX/4/256, 256>>>((const float4*)m, (__nv_bfloat162*)mhi,
                              (__nv_bfloat162*)mlo, NX/4);
    gemm_mma<<<gg, 256, gsm>>>(mhi, mlo, whi + 3*(size_t)NW, wlo + 3*(size_t)NW, bo, out, Dd, Dd);
}